// round 2
// baseline (speedup 1.0000x reference)
#include <cuda_runtime.h>

#define B 8
#define N 2048
#define BN (B * N)
#define ROWS 32          // rows per CTA tile: 32*2048*4B = 256KB, keeps L2 resident
#define TPB 512
#define DELTA 1e-7f

// Persistent scratch (__device__ globals per allocation rules).
// Ping-pong column-sum buffers keep colA/colB zeroed across graph replays.
__device__ float  g_odout1[BN];
__device__ float  g_odout2[BN];
__device__ float  g_pop1[BN];
__device__ float4 g_sir6[BN * 2];   // SIR after iter 0 (6 floats, padded to 8)
__device__ float  g_colA[BN * 4];   // iter0 colsums: [OD_in, SIR_in*3]  (zeroed by pass2)
__device__ float  g_colB[BN * 8];   // iter1 colsums: [OD_in, SIR_in*6, pad] (zeroed by final)

__device__ __forceinline__ float dnn(float num, float den) {
    return (den == 0.0f) ? 0.0f : num / den;
}

// ---------------------------------------------------------------------------
// Pass 1 (iteration idx=0, F=3). Reads input_feature directly (init fused).
// Phase 1: 16 warps x 2 rows -> row sums -> weights (float4) in SMEM.
// Phase 2: weighted column reduction; tile re-read hits L2 (256KB/CTA).
// ---------------------------------------------------------------------------
__global__ void __launch_bounds__(TPB, 2) pass1_kernel(
    const float* __restrict__ inp, const float* __restrict__ od_all)
{
    __shared__ float4 s_w[ROWS];

    const int b    = blockIdx.x >> 6;       // 64 tiles per batch (N/ROWS)
    const int tile = blockIdx.x & 63;
    const int i0   = tile * ROWS;
    const int tid  = threadIdx.x;
    const int warp = tid >> 5, lane = tid & 31;

    const float* OD = od_all + (size_t)(b * 2 + 0) * N * N;

    // -------- Phase 1 --------
#pragma unroll
    for (int q = 0; q < 2; q++) {
        const int rl = warp * 2 + q;
        const int i  = i0 + rl;
        const float4* row4 = reinterpret_cast<const float4*>(OD + (size_t)i * N);
        float sum = 0.0f;
#pragma unroll 4
        for (int t = lane; t < N / 4; t += 32) {
            float4 v = row4[t];
            sum += (v.x + v.y) + (v.z + v.w);
        }
#pragma unroll
        for (int o = 16; o; o >>= 1) sum += __shfl_xor_sync(0xffffffffu, sum, o);

        if (lane == 0) {
            const int gi = b * N + i;
            float4 f = reinterpret_cast<const float4*>(inp)[gi];
            float pop   = f.x;
            float ratio = dnn(pop, DELTA + sum);
            float s     = (ratio < 1.0f) ? ratio : 1.0f;
            g_odout1[gi] = s * sum;
            float dp = DELTA + pop;
            float4 w;
            w.x = s;
            w.y = s * dnn(f.y, dp);
            w.z = s * dnn(f.z, dp);
            w.w = s * dnn(f.w, dp);
            s_w[rl] = w;
        }
    }
    __syncthreads();

    // -------- Phase 2 --------
    const int j4 = tid * 4;
    float acc[4][4] = {};
    const float4* odb = reinterpret_cast<const float4*>(OD + (size_t)i0 * N) + tid;
#pragma unroll 4
    for (int r = 0; r < ROWS; r++) {
        float4 v = odb[r * (N / 4)];
        float4 w = s_w[r];
        float wk[4] = {w.x, w.y, w.z, w.w};
#pragma unroll
        for (int k = 0; k < 4; k++) {
            acc[0][k] = fmaf(v.x, wk[k], acc[0][k]);
            acc[1][k] = fmaf(v.y, wk[k], acc[1][k]);
            acc[2][k] = fmaf(v.z, wk[k], acc[2][k]);
            acc[3][k] = fmaf(v.w, wk[k], acc[3][k]);
        }
    }
#pragma unroll
    for (int c = 0; c < 4; c++) {
        float* dst = &g_colA[(size_t)(b * N + j4 + c) * 4];
#pragma unroll
        for (int k = 0; k < 4; k++) atomicAdd(dst + k, acc[c][k]);
    }
}

// ---------------------------------------------------------------------------
// Pass 2 (iteration idx=1, F=6). Fuses update<3>: per-row SIR6/pop1 derived
// from input + colA, colA re-zeroed for next replay. Writes colB + row state.
// ---------------------------------------------------------------------------
__global__ void __launch_bounds__(TPB, 2) pass2_kernel(
    const float* __restrict__ inp, const float* __restrict__ od_all)
{
    __shared__ float4 s_w0[ROWS];
    __shared__ float4 s_w1[ROWS];

    const int b    = blockIdx.x >> 6;
    const int tile = blockIdx.x & 63;
    const int i0   = tile * ROWS;
    const int tid  = threadIdx.x;
    const int warp = tid >> 5, lane = tid & 31;

    const float* OD = od_all + (size_t)(b * 2 + 1) * N * N;

    // -------- Phase 1: row sums + fused iter-0 state update --------
#pragma unroll
    for (int q = 0; q < 2; q++) {
        const int rl = warp * 2 + q;
        const int i  = i0 + rl;
        const float4* row4 = reinterpret_cast<const float4*>(OD + (size_t)i * N);
        float sum = 0.0f;
#pragma unroll 4
        for (int t = lane; t < N / 4; t += 32) {
            float4 v = row4[t];
            sum += (v.x + v.y) + (v.z + v.w);
        }
#pragma unroll
        for (int o = 16; o; o >>= 1) sum += __shfl_xor_sync(0xffffffffu, sum, o);

        if (lane == 0) {
            const int gi = b * N + i;
            float4 f   = reinterpret_cast<const float4*>(inp)[gi];
            float4 csA = reinterpret_cast<float4*>(g_colA)[gi];
            reinterpret_cast<float4*>(g_colA)[gi] = make_float4(0, 0, 0, 0); // re-zero
            float odout1 = g_odout1[gi];
            float pop0 = f.x;
            float dp0  = DELTA + pop0;
            float s6[6];
            s6[0] = f.y - odout1 * dnn(f.y, dp0);
            s6[1] = f.z - odout1 * dnn(f.z, dp0);
            s6[2] = f.w - odout1 * dnn(f.w, dp0);
            s6[3] = csA.y; s6[4] = csA.z; s6[5] = csA.w;
            float pop1 = pop0 - odout1 + csA.x;

            float ratio = dnn(pop1, DELTA + sum);
            float s     = (ratio < 1.0f) ? ratio : 1.0f;
            g_odout2[gi] = s * sum;
            g_pop1[gi]   = pop1;
            g_sir6[gi * 2 + 0] = make_float4(s6[0], s6[1], s6[2], s6[3]);
            g_sir6[gi * 2 + 1] = make_float4(s6[4], s6[5], 0, 0);

            float dp1 = DELTA + pop1;
            s_w0[rl] = make_float4(s,
                                   s * dnn(s6[0], dp1),
                                   s * dnn(s6[1], dp1),
                                   s * dnn(s6[2], dp1));
            s_w1[rl] = make_float4(s * dnn(s6[3], dp1),
                                   s * dnn(s6[4], dp1),
                                   s * dnn(s6[5], dp1), 0.0f);
        }
    }
    __syncthreads();

    // -------- Phase 2: K=7 weighted column reduction --------
    const int j4 = tid * 4;
    float acc[4][7] = {};
    const float4* odb = reinterpret_cast<const float4*>(OD + (size_t)i0 * N) + tid;
#pragma unroll 2
    for (int r = 0; r < ROWS; r++) {
        float4 v  = odb[r * (N / 4)];
        float4 wa = s_w0[r];
        float4 wb = s_w1[r];
        float wk[7] = {wa.x, wa.y, wa.z, wa.w, wb.x, wb.y, wb.z};
#pragma unroll
        for (int k = 0; k < 7; k++) {
            acc[0][k] = fmaf(v.x, wk[k], acc[0][k]);
            acc[1][k] = fmaf(v.y, wk[k], acc[1][k]);
            acc[2][k] = fmaf(v.z, wk[k], acc[2][k]);
            acc[3][k] = fmaf(v.w, wk[k], acc[3][k]);
        }
    }
#pragma unroll
    for (int c = 0; c < 4; c++) {
        float* dst = &g_colB[(size_t)(b * N + j4 + c) * 8];
#pragma unroll
        for (int k = 0; k < 7; k++) atomicAdd(dst + k, acc[c][k]);
    }
}

// ---------------------------------------------------------------------------
// Final: fuses update<6> + GEMM(12->64) + relu + concat(pop).
// Block handles 4 rows x 64 output channels. Re-zeros colB for next replay.
// ---------------------------------------------------------------------------
__global__ void __launch_bounds__(256) final_kernel(
    const float* __restrict__ kern,
    const float* __restrict__ bias,
    float* __restrict__ out)
{
    __shared__ float s_kern[12 * 64];
    const int tid = threadIdx.x;
    for (int t = tid; t < 12 * 64; t += 256) s_kern[t] = kern[t];
    __syncthreads();

    const int rowl = tid >> 6;
    const int c    = tid & 63;
    const int gi   = blockIdx.x * 4 + rowl;

    float pop1   = g_pop1[gi];
    float odout2 = g_odout2[gi];
    float4 a = g_sir6[gi * 2 + 0];
    float4 b4 = g_sir6[gi * 2 + 1];
    float4 cb0 = reinterpret_cast<const float4*>(g_colB)[gi * 2 + 0];
    float4 cb1 = reinterpret_cast<const float4*>(g_colB)[gi * 2 + 1];

    float dp1 = DELTA + pop1;
    float s12[12];
    s12[0] = a.x  - odout2 * dnn(a.x,  dp1);
    s12[1] = a.y  - odout2 * dnn(a.y,  dp1);
    s12[2] = a.z  - odout2 * dnn(a.z,  dp1);
    s12[3] = a.w  - odout2 * dnn(a.w,  dp1);
    s12[4] = b4.x - odout2 * dnn(b4.x, dp1);
    s12[5] = b4.y - odout2 * dnn(b4.y, dp1);
    s12[6]  = cb0.y; s12[7]  = cb0.z; s12[8] = cb0.w;
    s12[9]  = cb1.x; s12[10] = cb1.y; s12[11] = cb1.z;

    float acc = __ldg(&bias[c]);
#pragma unroll
    for (int f = 0; f < 12; f++)
        acc = fmaf(s12[f], s_kern[f * 64 + c], acc);
    acc = fmaxf(acc, 0.0f);

    float* orow = out + (size_t)gi * 65;
    orow[1 + c] = acc;
    if (c == 0) orow[0] = pop1 - odout2 + cb0.x;

    __syncthreads();               // everyone's colB reads done before re-zero
    if (c < 8) g_colB[gi * 8 + c] = 0.0f;
}

// ---------------------------------------------------------------------------
extern "C" void kernel_launch(void* const* d_in, const int* in_sizes, int n_in,
                              void* d_out, int out_size) {
    const float* inp  = (const float*)d_in[0];  // input_feature (8,2048,4)
    const float* od   = (const float*)d_in[1];  // OD_all (8,2,2048,2048)
    const float* kern = (const float*)d_in[2];  // kernel (12,64)
    const float* bias = (const float*)d_in[3];  // bias (64)
    float* out = (float*)d_out;                 // (8,2048,65)

    pass1_kernel<<<B * (N / ROWS), TPB>>>(inp, od);
    pass2_kernel<<<B * (N / ROWS), TPB>>>(inp, od);
    final_kernel<<<BN / 4, 256>>>(kern, bias, out);
}

// round 3
// speedup vs baseline: 2.0884x; 2.0884x over previous
#include <cuda_runtime.h>

#define B 8
#define N 2048
#define BN (B * N)
#define DELTA 1e-7f

#define TPB 512
#define CROWS 8                         // rows per chunk
#define CHUNK_FLOATS (CROWS * N)        // 16384 floats = 64KB
#define NCHUNKS (N / CROWS)             // 256 chunks per batch
#define CTAS_PER_B 18
#define GRID (B * CTAS_PER_B)           // 144 CTAs (1 per SM)
#define STAGES 3
#define MAXCH ((NCHUNKS + CTAS_PER_B - 1) / CTAS_PER_B)   // 15

// Persistent scratch (__device__ globals per allocation rules).
__device__ float  g_odout1[BN];
__device__ float  g_odout2[BN];
__device__ float  g_pop1[BN];
__device__ float4 g_sir6[BN * 2];   // SIR after iter 0 (6 floats in 2x float4)
__device__ float  g_colA[BN * 4];   // iter0 colsums [OD_in, SIR_in*3] (zeroed by pass2)
__device__ float  g_colB[BN * 8];   // iter1 colsums [OD_in, SIR_in*6, pad] (zeroed by final)

__device__ __forceinline__ float dnn(float n, float d) { return (d == 0.0f) ? 0.0f : n / d; }

__device__ __forceinline__ void cp_async16(float* s, const float* g) {
    unsigned sa = (unsigned)__cvta_generic_to_shared(s);
    asm volatile("cp.async.cg.shared.global [%0], [%1], 16;" :: "r"(sa), "l"(g));
}
__device__ __forceinline__ void cp_commit() { asm volatile("cp.async.commit_group;"); }
template<int Nw> __device__ __forceinline__ void cp_wait() {
    asm volatile("cp.async.wait_group %0;" :: "n"(Nw));
}

__device__ __forceinline__ void load_chunk(float* dst, const float* src, int tid) {
#pragma unroll
    for (int v = 0; v < CHUNK_FLOATS / 4 / TPB; v++)   // 8 x 16B per thread
        cp_async16(dst + (size_t)(tid + v * TPB) * 4, src + (size_t)(tid + v * TPB) * 4);
}

// ---------------------------------------------------------------------------
// Pass 1 (iteration 0, K=4). cp.async 3-stage pipeline over 8-row chunks.
// ---------------------------------------------------------------------------
__global__ void __launch_bounds__(TPB, 1) pass1_kernel(
    const float* __restrict__ inp, const float* __restrict__ od_all)
{
    extern __shared__ float sm[];
    float*  bufs = sm;                                                   // [3][16384]
    float4* s_w  = reinterpret_cast<float4*>(sm + STAGES * CHUNK_FLOATS); // [8]
    float4* s_st = s_w + CROWS;                                          // [MAXCH*8]

    const int b    = blockIdx.x / CTAS_PER_B;
    const int slot = blockIdx.x % CTAS_PER_B;
    const int tid  = threadIdx.x;
    const int warp = tid >> 5, lane = tid & 31;
    const float* OD = od_all + (size_t)(b * 2) * N * N;
    const int nch = (NCHUNKS - 1 - slot) / CTAS_PER_B + 1;   // 14 or 15

    // One-time prefetch of per-row state (input features) into smem
    for (int L = tid; L < nch * CROWS; L += TPB) {
        int i = (slot + (L >> 3) * CTAS_PER_B) * CROWS + (L & 7);
        s_st[L] = reinterpret_cast<const float4*>(inp)[b * N + i];
    }

    // Pipeline prologue (nch >= 14 > STAGES-1 always)
#pragma unroll
    for (int s = 0; s < STAGES - 1; s++) {
        load_chunk(bufs + s * CHUNK_FLOATS,
                   OD + (size_t)(slot + s * CTAS_PER_B) * CROWS * N, tid);
        cp_commit();
    }

    float acc[4][4] = {};
    for (int c = 0; c < nch; c++) {
        cp_wait<STAGES - 2>();
        __syncthreads();
        float* buf = bufs + (c % STAGES) * CHUNK_FLOATS;

        // Row sums + weights: warp w owns row w (smem-resident)
        if (warp < CROWS) {
            const float4* row = reinterpret_cast<const float4*>(buf + warp * N);
            float s = 0.0f;
#pragma unroll
            for (int t = lane; t < N / 4; t += 32) {
                float4 v = row[t];
                s += (v.x + v.y) + (v.z + v.w);
            }
#pragma unroll
            for (int o = 16; o; o >>= 1) s += __shfl_xor_sync(0xffffffffu, s, o);
            if (lane == 0) {
                float4 f = s_st[c * CROWS + warp];
                int gi = b * N + (slot + c * CTAS_PER_B) * CROWS + warp;
                float ratio = dnn(f.x, DELTA + s);
                float sc = ratio < 1.0f ? ratio : 1.0f;
                g_odout1[gi] = sc * s;
                float dp = DELTA + f.x;
                s_w[warp] = make_float4(sc, sc * dnn(f.y, dp),
                                        sc * dnn(f.z, dp), sc * dnn(f.w, dp));
            }
        }
        __syncthreads();

        // Weighted column accumulation: thread owns 4 consecutive cols
        const float4* colp = reinterpret_cast<const float4*>(buf) + tid;
#pragma unroll
        for (int r = 0; r < CROWS; r++) {
            float4 v = colp[r * (N / 4)];
            float4 w = s_w[r];
            float wk[4] = {w.x, w.y, w.z, w.w};
#pragma unroll
            for (int k = 0; k < 4; k++) {
                acc[0][k] = fmaf(v.x, wk[k], acc[0][k]);
                acc[1][k] = fmaf(v.y, wk[k], acc[1][k]);
                acc[2][k] = fmaf(v.z, wk[k], acc[2][k]);
                acc[3][k] = fmaf(v.w, wk[k], acc[3][k]);
            }
        }
        __syncthreads();   // buffer (c%STAGES) free for reuse

        int nc = c + STAGES - 1;
        if (nc < nch)
            load_chunk(bufs + (nc % STAGES) * CHUNK_FLOATS,
                       OD + (size_t)(slot + nc * CTAS_PER_B) * CROWS * N, tid);
        cp_commit();       // one group per iteration (possibly empty)
    }

    // Single flush per CTA
#pragma unroll
    for (int cc = 0; cc < 4; cc++) {
        float* dst = g_colA + ((size_t)b * N + tid * 4 + cc) * 4;
#pragma unroll
        for (int k = 0; k < 4; k++) atomicAdd(dst + k, acc[cc][k]);
    }
}

// ---------------------------------------------------------------------------
// Pass 2 (iteration 1, K=7). Fuses update<3> in the one-time state prefetch.
// ---------------------------------------------------------------------------
__global__ void __launch_bounds__(TPB, 1) pass2_kernel(
    const float* __restrict__ inp, const float* __restrict__ od_all)
{
    extern __shared__ float sm[];
    float*  bufs = sm;
    float4* s_w0 = reinterpret_cast<float4*>(sm + STAGES * CHUNK_FLOATS); // [8]
    float4* s_w1 = s_w0 + CROWS;                                          // [8]
    float4* s_st = s_w1 + CROWS;                                          // [MAXCH*8*2]

    const int b    = blockIdx.x / CTAS_PER_B;
    const int slot = blockIdx.x % CTAS_PER_B;
    const int tid  = threadIdx.x;
    const int warp = tid >> 5, lane = tid & 31;
    const float* OD = od_all + (size_t)(b * 2 + 1) * N * N;
    const int nch = (NCHUNKS - 1 - slot) / CTAS_PER_B + 1;

    // One-time prefetch + fused iter-0 state update; re-zero colA for replay
    for (int L = tid; L < nch * CROWS; L += TPB) {
        int i  = (slot + (L >> 3) * CTAS_PER_B) * CROWS + (L & 7);
        int gi = b * N + i;
        float4 f   = reinterpret_cast<const float4*>(inp)[gi];
        float4 csA = reinterpret_cast<float4*>(g_colA)[gi];
        reinterpret_cast<float4*>(g_colA)[gi] = make_float4(0, 0, 0, 0);
        float od1 = g_odout1[gi];
        float dp0 = DELTA + f.x;
        float s60 = f.y - od1 * dnn(f.y, dp0);
        float s61 = f.z - od1 * dnn(f.z, dp0);
        float s62 = f.w - od1 * dnn(f.w, dp0);
        float pop1 = f.x - od1 + csA.x;
        s_st[L * 2 + 0] = make_float4(pop1, s60, s61, s62);
        s_st[L * 2 + 1] = make_float4(csA.y, csA.z, csA.w, 0.0f);
        g_pop1[gi] = pop1;
        g_sir6[gi * 2 + 0] = make_float4(s60, s61, s62, csA.y);
        g_sir6[gi * 2 + 1] = make_float4(csA.z, csA.w, 0.0f, 0.0f);
    }

#pragma unroll
    for (int s = 0; s < STAGES - 1; s++) {
        load_chunk(bufs + s * CHUNK_FLOATS,
                   OD + (size_t)(slot + s * CTAS_PER_B) * CROWS * N, tid);
        cp_commit();
    }

    float acc[4][7] = {};
    for (int c = 0; c < nch; c++) {
        cp_wait<STAGES - 2>();
        __syncthreads();
        float* buf = bufs + (c % STAGES) * CHUNK_FLOATS;

        if (warp < CROWS) {
            const float4* row = reinterpret_cast<const float4*>(buf + warp * N);
            float s = 0.0f;
#pragma unroll
            for (int t = lane; t < N / 4; t += 32) {
                float4 v = row[t];
                s += (v.x + v.y) + (v.z + v.w);
            }
#pragma unroll
            for (int o = 16; o; o >>= 1) s += __shfl_xor_sync(0xffffffffu, s, o);
            if (lane == 0) {
                float4 a  = s_st[(c * CROWS + warp) * 2 + 0];  // pop1, s6[0..2]
                float4 bb = s_st[(c * CROWS + warp) * 2 + 1];  // s6[3..5]
                int gi = b * N + (slot + c * CTAS_PER_B) * CROWS + warp;
                float ratio = dnn(a.x, DELTA + s);
                float sc = ratio < 1.0f ? ratio : 1.0f;
                g_odout2[gi] = sc * s;
                float dp1 = DELTA + a.x;
                s_w0[warp] = make_float4(sc, sc * dnn(a.y, dp1),
                                         sc * dnn(a.z, dp1), sc * dnn(a.w, dp1));
                s_w1[warp] = make_float4(sc * dnn(bb.x, dp1), sc * dnn(bb.y, dp1),
                                         sc * dnn(bb.z, dp1), 0.0f);
            }
        }
        __syncthreads();

        const float4* colp = reinterpret_cast<const float4*>(buf) + tid;
#pragma unroll
        for (int r = 0; r < CROWS; r++) {
            float4 v  = colp[r * (N / 4)];
            float4 wa = s_w0[r];
            float4 wb = s_w1[r];
            float wk[7] = {wa.x, wa.y, wa.z, wa.w, wb.x, wb.y, wb.z};
#pragma unroll
            for (int k = 0; k < 7; k++) {
                acc[0][k] = fmaf(v.x, wk[k], acc[0][k]);
                acc[1][k] = fmaf(v.y, wk[k], acc[1][k]);
                acc[2][k] = fmaf(v.z, wk[k], acc[2][k]);
                acc[3][k] = fmaf(v.w, wk[k], acc[3][k]);
            }
        }
        __syncthreads();

        int nc = c + STAGES - 1;
        if (nc < nch)
            load_chunk(bufs + (nc % STAGES) * CHUNK_FLOATS,
                       OD + (size_t)(slot + nc * CTAS_PER_B) * CROWS * N, tid);
        cp_commit();
    }

#pragma unroll
    for (int cc = 0; cc < 4; cc++) {
        float* dst = g_colB + ((size_t)b * N + tid * 4 + cc) * 8;
#pragma unroll
        for (int k = 0; k < 7; k++) atomicAdd(dst + k, acc[cc][k]);
    }
}

// ---------------------------------------------------------------------------
// Final: fuses update<6> + GEMM(12->64) + relu + concat(pop). Re-zeros colB.
// ---------------------------------------------------------------------------
__global__ void __launch_bounds__(256) final_kernel(
    const float* __restrict__ kern,
    const float* __restrict__ bias,
    float* __restrict__ out)
{
    __shared__ float s_kern[12 * 64];
    const int tid = threadIdx.x;
    for (int t = tid; t < 12 * 64; t += 256) s_kern[t] = kern[t];
    __syncthreads();

    const int rowl = tid >> 6;
    const int c    = tid & 63;
    const int gi   = blockIdx.x * 4 + rowl;

    float pop1   = g_pop1[gi];
    float odout2 = g_odout2[gi];
    float4 a   = g_sir6[gi * 2 + 0];
    float4 b4  = g_sir6[gi * 2 + 1];
    float4 cb0 = reinterpret_cast<const float4*>(g_colB)[gi * 2 + 0];
    float4 cb1 = reinterpret_cast<const float4*>(g_colB)[gi * 2 + 1];

    float dp1 = DELTA + pop1;
    float s12[12];
    s12[0] = a.x  - odout2 * dnn(a.x,  dp1);
    s12[1] = a.y  - odout2 * dnn(a.y,  dp1);
    s12[2] = a.z  - odout2 * dnn(a.z,  dp1);
    s12[3] = a.w  - odout2 * dnn(a.w,  dp1);
    s12[4] = b4.x - odout2 * dnn(b4.x, dp1);
    s12[5] = b4.y - odout2 * dnn(b4.y, dp1);
    s12[6]  = cb0.y; s12[7]  = cb0.z; s12[8]  = cb0.w;
    s12[9]  = cb1.x; s12[10] = cb1.y; s12[11] = cb1.z;

    float acc = __ldg(&bias[c]);
#pragma unroll
    for (int f = 0; f < 12; f++)
        acc = fmaf(s12[f], s_kern[f * 64 + c], acc);
    acc = fmaxf(acc, 0.0f);

    float* orow = out + (size_t)gi * 65;
    orow[1 + c] = acc;
    if (c == 0) orow[0] = pop1 - odout2 + cb0.x;

    __syncthreads();                  // all colB reads done before re-zero
    if (c < 8) g_colB[gi * 8 + c] = 0.0f;
}

// ---------------------------------------------------------------------------
extern "C" void kernel_launch(void* const* d_in, const int* in_sizes, int n_in,
                              void* d_out, int out_size) {
    const float* inp  = (const float*)d_in[0];  // input_feature (8,2048,4)
    const float* od   = (const float*)d_in[1];  // OD_all (8,2,2048,2048)
    const float* kern = (const float*)d_in[2];  // kernel (12,64)
    const float* bias = (const float*)d_in[3];  // bias (64)
    float* out = (float*)d_out;                 // (8,2048,65)

    const int SMEM1 = STAGES * CHUNK_FLOATS * 4 + CROWS * 16 + MAXCH * CROWS * 16;
    const int SMEM2 = STAGES * CHUNK_FLOATS * 4 + 2 * CROWS * 16 + MAXCH * CROWS * 32;

    cudaFuncSetAttribute(pass1_kernel, cudaFuncAttributeMaxDynamicSharedMemorySize, SMEM1);
    cudaFuncSetAttribute(pass2_kernel, cudaFuncAttributeMaxDynamicSharedMemorySize, SMEM2);

    pass1_kernel<<<GRID, TPB, SMEM1>>>(inp, od);
    pass2_kernel<<<GRID, TPB, SMEM2>>>(inp, od);
    final_kernel<<<BN / 4, 256>>>(kern, bias, out);
}